// round 1
// baseline (speedup 1.0000x reference)
#include <cuda_runtime.h>

// GRU masked scan: B=4096 independent scalar recurrences of length T=4096.
// Latency-bound on the per-step serial chain:
//   fma(h) [4] -> MUFU.TANH [16] -> fma [4] -> MUFU.TANH [16] -> fma [4]  = 44 cyc/step
// sigmoid folded as 0.5*tanh(0.5v)+0.5 with all 0.5 factors/biases pre-folded
// into constants. Mask folded as z_eff = (x!=0) ? z : 1  =>  h' = h exactly.

#define T_LEN 4096

__device__ __forceinline__ float tanha(float v) {
    float y;
    asm("tanh.approx.f32 %0, %1;" : "=f"(y) : "f"(v));
    return y;
}

__global__ __launch_bounds__(32, 1) void gru_scan_kernel(
    const float* __restrict__ x,
    const float* __restrict__ kern,
    const float* __restrict__ rkern,
    const float* __restrict__ bias,
    float* __restrict__ out,
    int B)
{
    const int b = blockIdx.x * blockDim.x + threadIdx.x;
    if (b >= B) return;

    // Scalar weights (UNITS=1, F=1): kernel (1,3), recurrent_kernel (1,3), bias (2,3)
    const float k0 = kern[0],  k1 = kern[1],  k2 = kern[2];
    const float r0 = rkern[0], r1 = rkern[1], r2 = rkern[2];
    const float bi0 = bias[0], bi1 = bias[1], bi2 = bias[2];
    const float br0 = bias[3], br1 = bias[4], br2 = bias[5];

    // z gate: z = sigmoid(x*k0 + bi0 + h*r0 + br0) = 0.5*tanh(0.5*(...)) + 0.5
    const float cz_x = 0.5f * k0, cz_h = 0.5f * r0, cz_b = 0.5f * (bi0 + br0);
    // r gate: same folding
    const float cr_x = 0.5f * k1, cr_h = 0.5f * r1, cr_b = 0.5f * (bi1 + br1);
    // q = 0.5*rhh = 0.5*(h*r2 + br2);  hh_arg = xh + r*rhh = fma(r_tanh, q, xh + q)
    const float q_h = 0.5f * r2, q_b = 0.5f * br2;
    const float ch_x = k2, ch_b = bi2;

    const float4* __restrict__ xp =
        reinterpret_cast<const float4*>(x + (size_t)b * T_LEN);
    const int NV = T_LEN / 4;  // 1024 float4 per row

    float h = 0.0f;

#define GRU_STEP(XT) do {                                        \
        const float xt_ = (XT);                                  \
        float xpz  = fmaf(xt_, cz_x, cz_b);                      \
        float xpr  = fmaf(xt_, cr_x, cr_b);                      \
        float xh   = fmaf(xt_, ch_x, ch_b);                      \
        float zarg = fmaf(h, cz_h, xpz);                         \
        float rarg = fmaf(h, cr_h, xpr);   /* critical: fma 4 */ \
        float q    = fmaf(h, q_h,  q_b);                         \
        float zt   = tanha(zarg);          /* off-path tanh   */ \
        float rt   = tanha(rarg);          /* critical: 16    */ \
        float base = xh + q;                                     \
        float zc   = fmaf(zt, 0.5f, 0.5f);                       \
        zc = (xt_ != 0.0f) ? zc : 1.0f;    /* mask fold       */ \
        float harg = fmaf(rt, q, base);    /* critical: fma 4 */ \
        float hh   = tanha(harg);          /* critical: 16    */ \
        float zh   = zc * h;                                     \
        float omz  = 1.0f - zc;                                  \
        h = fmaf(omz, hh, zh);             /* critical: fma 4 */ \
    } while (0)

    // Software-pipelined: 4 float4 in flight => 16-step (~700 cyc) prefetch
    // distance, covers DRAM latency off the dependency chain.
    float4 b0 = xp[0], b1 = xp[1], b2 = xp[2], b3 = xp[3];

    for (int i = 0; i < NV; i += 4) {
        int p0 = i + 4; if (p0 > NV - 1) p0 = NV - 1;
        int p1 = i + 5; if (p1 > NV - 1) p1 = NV - 1;
        int p2 = i + 6; if (p2 > NV - 1) p2 = NV - 1;
        int p3 = i + 7; if (p3 > NV - 1) p3 = NV - 1;
        float4 n0 = xp[p0];
        float4 n1 = xp[p1];
        float4 n2 = xp[p2];
        float4 n3 = xp[p3];

        GRU_STEP(b0.x); GRU_STEP(b0.y); GRU_STEP(b0.z); GRU_STEP(b0.w);
        GRU_STEP(b1.x); GRU_STEP(b1.y); GRU_STEP(b1.z); GRU_STEP(b1.w);
        GRU_STEP(b2.x); GRU_STEP(b2.y); GRU_STEP(b2.z); GRU_STEP(b2.w);
        GRU_STEP(b3.x); GRU_STEP(b3.y); GRU_STEP(b3.z); GRU_STEP(b3.w);

        b0 = n0; b1 = n1; b2 = n2; b3 = n3;
    }

#undef GRU_STEP

    out[b] = h;
}

extern "C" void kernel_launch(void* const* d_in, const int* in_sizes, int n_in,
                              void* d_out, int out_size)
{
    const float* x    = (const float*)d_in[0];
    const float* k    = (const float*)d_in[1];
    const float* rk   = (const float*)d_in[2];
    const float* bias = (const float*)d_in[3];
    float* out = (float*)d_out;

    const int B = out_size;  // B * UNITS = 4096
    const int threads = 32;
    const int blocks = (B + threads - 1) / threads;  // 128 blocks -> 1 warp/SM
    gru_scan_kernel<<<blocks, threads>>>(x, k, rk, bias, out, B);
}